// round 15
// baseline (speedup 1.0000x reference)
#include <cuda_runtime.h>
#include <cuda_bf16.h>
#include <cuda_fp16.h>
#include <math.h>
#include <stdint.h>

#define NROWS 16384      // B*L = 32*512
#define Hh 132           // hidden dim

// scratch (static device globals are allowed)
__device__ float  g_hv [NROWS*Hh];
__device__ float4 g_misc[NROWS];          // dg, dg2, dl, dl2
__device__ float  g_u  [NROWS*Hh];        // hidden @ W_in.T
// fp16 image of W_noise, [n=136 pad][k stride 152], zero-padded
__device__ __align__(16) __half g_Bf[136*152];
// pre-generated noise tiles: per pair 112 rows x 304B (k stride 152 fp16), pads zeroed
__device__ __align__(16) uint2 g_noise[(size_t)8192*4256];   // 279 MB

// ---------------------------------------------------------------- kernel 1
// blocks [0,512): positional/type prep (32 rows each); blocks [512,593): W image
__global__ void k_prep(const int* __restrict__ etype,
                       const float* __restrict__ etime,
                       const float* __restrict__ Wt,
                       const float* __restrict__ temb,
                       const float* __restrict__ Wg,
                       const float* __restrict__ Wl,
                       const float* __restrict__ Wn)
{
    int bx = blockIdx.x;
    int tid = threadIdx.x;
    if (bx >= 512){
        int idx = (bx - 512)*256 + tid;
        if (idx >= 136*152) return;
        int n = idx / 152, k = idx % 152;
        float v = (n < 132 && k < 132) ? Wn[n*132 + k] : 0.f;
        g_Bf[idx] = __float2half_rn(v);
        return;
    }
    int k  = tid & 63;
    int rg = tid >> 6;               // 0..3
    float argf = (float)(2*k) * (-0.07195578415606393f);
    float dv   = (float)exp((double)argf);   // one FP64 exp per thread
    float wtk  = Wt[k];
    int row0 = bx*32 + rg*8;
    #pragma unroll 1
    for (int rr = 0; rr < 8; rr++){
        int row = row0 + rr;
        int l   = row & 511;
        float t   = etime[row];
        float phi = __fmul_rn(t, wtk);
        float arc = __fmul_rn((float)l, dv);
        float x   = __fadd_rn(arc, phi);     // identical f32 value as reference
        double xd = (double)x;
        double q  = rint(xd * 0.15915494309189535);
        double r  = xd - q*6.283185307179586477;
        r -= q*2.4492935982947064e-16;
        float rf = (float)r;
        float s, c;
        __sincosf(rf, &s, &c);
        g_hv[row*Hh + k]      = s;
        g_hv[row*Hh + 64 + k] = c;
        int ty = etype[row];
        if (k < 4) g_hv[row*Hh + 128 + k] = temb[ty*4 + k];
        if (k == 0){
            float te0=temb[ty*4+0], te1=temb[ty*4+1], te2=temb[ty*4+2], te3=temb[ty*4+3];
            float dg  = te0*Wg[0]+te1*Wg[1]+te2*Wg[2]+te3*Wg[3];
            float dg2 = te0*Wg[4]+te1*Wg[5]+te2*Wg[6]+te3*Wg[7];
            float dl  = te0*Wl[0]+te1*Wl[1]+te2*Wl[2]+te3*Wl[3];
            float dl2 = te0*Wl[4]+te1*Wl[5]+te2*Wl[6]+te3*Wl[7];
            g_misc[row] = make_float4(dg, dg2, dl, dl2);
        }
    }
}

// ---------------------------------------------------------------- RNG
__device__ __forceinline__ void tf_round(uint32_t& x0, uint32_t& x1, int r){
    x0 += x1; x1 = __funnelshift_l(x1, x1, r); x1 ^= x0;
}
__device__ __forceinline__ float tf_uniform(uint32_t idx){
    const uint32_t k0 = 0u, k1 = 42u, k2 = 0x1BD11BDAu ^ 42u;
    uint32_t x0 = 0u, x1 = idx;
    x0 += k0; x1 += k1;
    tf_round(x0,x1,13); tf_round(x0,x1,15); tf_round(x0,x1,26); tf_round(x0,x1, 6);
    x0 += k1; x1 += k2 + 1u;
    tf_round(x0,x1,17); tf_round(x0,x1,29); tf_round(x0,x1,16); tf_round(x0,x1,24);
    x0 += k2; x1 += k0 + 2u;
    tf_round(x0,x1,13); tf_round(x0,x1,15); tf_round(x0,x1,26); tf_round(x0,x1, 6);
    x0 += k0; x1 += k1 + 3u;
    tf_round(x0,x1,17); tf_round(x0,x1,29); tf_round(x0,x1,16); tf_round(x0,x1,24);
    x0 += k1; x1 += k2 + 4u;
    tf_round(x0,x1,13); tf_round(x0,x1,15); tf_round(x0,x1,26); tf_round(x0,x1, 6);
    x0 += k2; x1 += k0 + 5u;
    uint32_t bits = x0 ^ x1;
    return __uint_as_float((bits >> 9) | 0x3f800000u) - 1.0f;
}

// fill one pair's noise tile in gmem (112 rows x 304B, pads zero), fp16
// incremental row/grp stepping (no per-iteration division)
__device__ __forceinline__ void rng_pair_gmem(int pair, int t){
    uint2* dst = g_noise + (size_t)pair*4256;
    uint32_t base = (uint32_t)pair * 13200u;
    unsigned row = (unsigned)t / 33u;
    unsigned grp = (unsigned)t - row*33u;
    for (unsigned e = t; e < 3300u; e += 256){
        uint32_t idx = base + row*132u + grp*4u;
        float f0 = tf_uniform(idx);
        float f1 = tf_uniform(idx + 1u);
        float f2 = tf_uniform(idx + 2u);
        float f3 = tf_uniform(idx + 3u);
        __half2 h01 = __floats2half2_rn(f0, f1);
        __half2 h23 = __floats2half2_rn(f2, f3);
        dst[row*38u + grp] = make_uint2(*(uint32_t*)&h01, *(uint32_t*)&h23);
        // e += 256 == 7*33 + 25
        grp += 25u; row += 7u;
        if (grp >= 33u){ grp -= 33u; row += 1u; }
    }
    // pads: k in [132,152) for rows 0..99 (5 uint2/row), rows 100..111 full (456 uint2)
    for (unsigned e = t; e < 956u; e += 256){
        unsigned o;
        if (e < 500u){ unsigned r2 = e/5u, q = e - r2*5u; o = r2*38u + 33u + q; }
        else o = 3800u + (e - 500u);
        dst[o] = make_uint2(0u, 0u);
    }
}

// ---------------------------------------------------------------- kernel 1b
// dedicated RNG launch: zero smem -> high occupancy, alu pipe saturates
__global__ void __launch_bounds__(256)
k_rng()
{
    int idx = blockIdx.x;                 // 0..4095
    int tid = threadIdx.x;
    rng_pair_gmem(2*idx,     tid);
    rng_pair_gmem(2*idx + 1, tid);
}

// ---------------------------------------------------------------- kernel 2
// attention + LayerNorm + head (u GEMM + mark softmax); grid = 512
#define AT_HV   0          // 4224 (32x132)
#define AT_SCS  4224       // 1056 (32x33)
#define AT_WIN  5280       // 17424 (WinT [k][132])
#define AT_WP   22704      // 2640  (WpT  [k][20])
#define AT_MIS  25344      // 192: tj,dgj,dlj,tis,dg2s,dl2s
#define AT_FLOATS 25536    // 102144 bytes
__global__ void k_attn(const float* __restrict__ etime,
                       const float* __restrict__ bgp,
                       const float* __restrict__ blp,
                       const float* __restrict__ gamma,
                       const float* __restrict__ beta,
                       const float* __restrict__ W_in,
                       const float* __restrict__ W_pred,
                       float* __restrict__ out_mark)
{
    extern __shared__ __align__(16) float smA[];
    int bx = blockIdx.x;
    int tid = threadIdx.x;
    float* hvsh = smA + AT_HV;
    float* scs  = smA + AT_SCS;
    float* WinT = smA + AT_WIN;
    float* WpT  = smA + AT_WP;
    float* tj   = smA + AT_MIS;
    float* dgj  = tj + 32;
    float* dlj  = dgj + 32;
    float* tis  = dlj + 32;
    float* dg2s = tis + 32;
    float* dl2s = dg2s + 32;

    int it = bx & 15, b = bx >> 4;
    int i0 = it*32;
    int g = tid >> 5, lane = tid & 31;
    float bg = bgp[0], bl = blp[0];
    if (tid < 32){
        int ri = b*512 + i0 + tid;
        tis[tid] = etime[ri];
        float4 m = g_misc[ri];
        dg2s[tid] = m.y; dl2s[tid] = m.w;
    }
    // stage W_in^T and W_pred^T
    for (int o = tid; o < 17424; o += 256){
        float v = W_in[o];  int hp = o/132, k = o%132;
        WinT[k*132 + hp] = v;
    }
    for (int o = tid; o < 2640; o += 256){
        float v = W_pred[o]; int c = o/132, k = o%132;
        WpT[k*20 + c] = v;
    }
    float acc[20];
    #pragma unroll
    for (int m=0;m<20;m++) acc[m]=0.f;
    int c0 = g*4;     // warp g owns float4 groups c0..c0+3 (+1 extra for g==7)

    for (int jt = 0; jt <= it; jt++) {
        int j0 = jt*32;
        __syncthreads();                         // prev FMA done; tis ready
        {
            const float4* src4 = (const float4*)(g_hv + (size_t)(b*512 + j0)*132);
            float4* d4 = (float4*)hvsh;
            for (int o = tid; o < 1056; o += 256) d4[o] = src4[o];
        }
        if (tid < 32) {
            int rj = b*512 + j0 + tid;
            tj[tid] = etime[rj];
            float4 mj = g_misc[rj];
            dgj[tid] = mj.x; dlj[tid] = mj.z;
        }
        __syncthreads();
        // score phase: 1024 scores over 256 threads (computed ONCE per tile)
        #pragma unroll
        for (int e = tid; e < 1024; e += 256){
            int ii = e >> 5, jj = e & 31;
            float td  = fabsf(tj[jj] - tis[ii]);
            float gg  = dgj[jj] + dg2s[ii] + bg;
            float sig = 1.f/(1.f + expf(-gg));
            float ll  = dlj[jj] + dl2s[ii] + bl;
            float spv = fmaxf(ll,0.f) + log1pf(expf(-fabsf(ll)));
            float ls  = spv + 1e-6f;
            float sc  = sig / (1.f + td*td/(2.f*ls*ls));
            scs[ii*33 + jj] = (j0 + jj < i0 + ii) ? sc : 0.f;
        }
        __syncthreads();
        #pragma unroll 1
        for (int j = 0; j < 32; j++) {
            float sc = scs[lane*33 + j];
            const float4* hv4 = (const float4*)hvsh + j*33 + c0;
            float4 v0 = hv4[0], v1 = hv4[1], v2 = hv4[2], v3 = hv4[3];
            acc[0]+=sc*v0.x;  acc[1]+=sc*v0.y;  acc[2]+=sc*v0.z;  acc[3]+=sc*v0.w;
            acc[4]+=sc*v1.x;  acc[5]+=sc*v1.y;  acc[6]+=sc*v1.z;  acc[7]+=sc*v1.w;
            acc[8]+=sc*v2.x;  acc[9]+=sc*v2.y;  acc[10]+=sc*v2.z; acc[11]+=sc*v2.w;
            acc[12]+=sc*v3.x; acc[13]+=sc*v3.y; acc[14]+=sc*v3.z; acc[15]+=sc*v3.w;
            if (g == 7){
                float4 v4 = hv4[4];
                acc[16]+=sc*v4.x; acc[17]+=sc*v4.y; acc[18]+=sc*v4.z; acc[19]+=sc*v4.w;
            }
        }
    }
    __syncthreads();
    {
        float4* w4 = (float4*)hvsh + lane*33 + c0;
        w4[0] = make_float4(acc[0],acc[1],acc[2],acc[3]);
        w4[1] = make_float4(acc[4],acc[5],acc[6],acc[7]);
        w4[2] = make_float4(acc[8],acc[9],acc[10],acc[11]);
        w4[3] = make_float4(acc[12],acc[13],acc[14],acc[15]);
        if (g == 7) w4[4] = make_float4(acc[16],acc[17],acc[18],acc[19]);
    }
    __syncthreads();
    // LayerNorm in place (warp-private rows g*4..g*4+3)
    for (int rr=0; rr<4; rr++) {
        int rloc = g*4+rr;
        float s = 0.f;
        #pragma unroll
        for (int q=0;q<5;q++){ int h=lane+32*q; if(h<Hh) s += hvsh[rloc*Hh+h]; }
        #pragma unroll
        for (int off=16;off>0;off>>=1) s += __shfl_xor_sync(0xffffffffu, s, off);
        float mu = s * (1.f/132.f);
        float v = 0.f;
        #pragma unroll
        for (int q=0;q<5;q++){ int h=lane+32*q; if(h<Hh){ float d=hvsh[rloc*Hh+h]-mu; v += d*d; } }
        #pragma unroll
        for (int off=16;off>0;off>>=1) v += __shfl_xor_sync(0xffffffffu, v, off);
        float rs = rsqrtf(v*(1.f/132.f) + 1e-6f);
        #pragma unroll
        for (int q=0;q<5;q++){
            int h=lane+32*q;
            if (h<Hh) hvsh[rloc*Hh+h] = (hvsh[rloc*Hh+h]-mu)*rs*gamma[h] + beta[h];
        }
    }
    __syncwarp();
    // head: u = hid @ W_in^T (store g_u), mark softmax (output)
    #pragma unroll 1
    for (int rr=0; rr<4; rr++){
        int rloc = g*4+rr;
        int row  = b*512 + i0 + rloc;
        float4 a4 = make_float4(0.f,0.f,0.f,0.f);
        float aex = 0.f, lg = 0.f;
        #pragma unroll 2
        for (int k=0;k<132;k++){
            float hk = hvsh[rloc*132+k];
            float4 wv = *(const float4*)(WinT + k*132 + 4*lane);
            a4.x += hk*wv.x; a4.y += hk*wv.y; a4.z += hk*wv.z; a4.w += hk*wv.w;
            if (lane < 4)  aex += hk * WinT[k*132 + 128 + lane];
            if (lane < 20) lg  += hk * WpT[k*20 + lane];
        }
        *(float4*)(g_u + (size_t)row*132 + 4*lane) = a4;
        if (lane < 4) g_u[(size_t)row*132 + 128 + lane] = aex;
        float v = (lane<20) ? lg : -3.4e38f;
        #pragma unroll
        for (int off=16;off>0;off>>=1) v = fmaxf(v, __shfl_xor_sync(0xffffffffu, v, off));
        float e = (lane<20) ? expf(lg - v) : 0.f;
        float ssum = e;
        #pragma unroll
        for (int off=16;off>0;off>>=1) ssum += __shfl_xor_sync(0xffffffffu, ssum, off);
        if (lane<20) out_mark[(size_t)row*20+lane] = e/ssum;
    }
}

// ---------------------------------------------------------------- kernel 4
// A (noise) layout: [row 0..111][k stride 152] fp16, 304B row stride.
#define SM_A0   0
#define SM_A1   34048
#define SM_B    68096        // fp16 W image, 41344 bytes
#define SM_U    109440       // [2][272] floats (264 used + zero pad)
#define SM_WT   111616       // 136 floats (132..135 = 0)
#define SM_PSH  112160       // [2][112] partial row sums
#define SM_SPS  113056       // 112 floats (rows 0..99 used)
#define SM_TOT  113504

__device__ __forceinline__ uint32_t smem_u32(const void* p){
    uint32_t a;
    asm("{ .reg .u64 t; cvta.to.shared.u64 t, %1; cvt.u32.u64 %0, t; }" : "=r"(a) : "l"(p));
    return a;
}

__device__ __forceinline__ void prefetch(uint32_t sb, int buf, int pair, int tid){
    const uint4* src = ((const uint4*)g_noise) + (size_t)pair*2128;
    uint32_t dst = sb + SM_A0 + buf*34048;
    #pragma unroll 1
    for (int o = tid; o < 2128; o += 512)
        asm volatile("cp.async.cg.shared.global [%0], [%1], 16;"
                     :: "r"(dst + o*16), "l"(src + o));
    if (tid < 66){
        const uint4* us = (const uint4*)(g_u + (size_t)pair*264) + tid;
        asm volatile("cp.async.cg.shared.global [%0], [%1], 16;"
                     :: "r"(sb + SM_U + buf*1088 + tid*16), "l"(us));
    }
}

template<int CNT>
__device__ __forceinline__ void do_chunk(
    uint32_t b_base, int nbase,
    const uint32_t af[9][4],
    const float* u_lo, const float* u_hi, const float* wts,
    int lq, float& p_lo, float& p_hi)
{
    float d[CNT][4];
    #pragma unroll
    for (int j=0;j<CNT;j++){ d[j][0]=0.f; d[j][1]=0.f; d[j][2]=0.f; d[j][3]=0.f; }
    #pragma unroll
    for (int j=0;j<CNT;j++){
        uint32_t bo = (uint32_t)((nbase+j)*2432);
        #pragma unroll
        for (int k=0;k<9;k++){
            uint32_t b0,b1;
            asm volatile("ldmatrix.sync.aligned.m8n8.x2.shared.b16 {%0,%1}, [%2];"
                : "=r"(b0),"=r"(b1) : "r"(b_base + bo + (uint32_t)(k*32)));
            asm("mma.sync.aligned.m16n8k16.row.col.f32.f16.f16.f32 "
                "{%0,%1,%2,%3}, {%4,%5,%6,%7}, {%8,%9}, {%0,%1,%2,%3};"
                : "+f"(d[j][0]),"+f"(d[j][1]),"+f"(d[j][2]),"+f"(d[j][3])
                : "r"(af[k][0]),"r"(af[k][1]),"r"(af[k][2]),"r"(af[k][3]),
                  "r"(b0),"r"(b1));
        }
    }
    #pragma unroll
    for (int j=0;j<CNT;j++){
        int c0 = (nbase+j)*8 + lq*2;
        float w0 = wts[c0], w1 = wts[c0+1];
        p_lo += fmaxf(d[j][0]+u_lo[c0],0.f)*w0 + fmaxf(d[j][1]+u_lo[c0+1],0.f)*w1;
        p_hi += fmaxf(d[j][2]+u_hi[c0],0.f)*w0 + fmaxf(d[j][3]+u_hi[c0+1],0.f)*w1;
    }
}

__global__ void __launch_bounds__(512, 1)
k_gan(const float* __restrict__ w_time, float* __restrict__ out_mean)
{
    extern __shared__ char smc[];
    uint32_t sb = smem_u32(smc);
    int tid = threadIdx.x;
    int wid = tid >> 5, lane = tid & 31;
    int bid = blockIdx.x;

    // init: copy B image, wt, zero ONLY u pad words (live u words are cp.async targets)
    {
        const uint4* sB = (const uint4*)g_Bf;
        uint4* dB = (uint4*)(smc + SM_B);
        for (int o = tid; o < 2584; o += 512) dB[o] = sB[o];
        float* wt = (float*)(smc + SM_WT);
        if (tid < 136) wt[tid] = (tid < 132) ? w_time[tid] : 0.f;
        float* uu = (float*)(smc + SM_U);
        if (tid < 8){ uu[264 + tid] = 0.f; uu[536 + tid] = 0.f; }
    }
    __syncthreads();   // init stores complete before async writes to SM_U region
    // prologue prefetch (buf 0)
    prefetch(sb, 0, bid, tid);
    asm volatile("cp.async.commit_group;" ::: "memory");

    for (int iter = 0;; iter++){
        int pair = bid + 148*iter;
        if (pair >= 8192) break;
        int buf = iter & 1;
        int nextpair = pair + 148;

        if (nextpair < 8192){
            prefetch(sb, buf^1, nextpair, tid);
            asm volatile("cp.async.commit_group;" ::: "memory");
            asm volatile("cp.async.wait_group 1;" ::: "memory");
        } else {
            asm volatile("cp.async.wait_group 0;" ::: "memory");
        }
        __syncthreads();       // A(buf), u(buf) visible to all threads

        if (wid < 14){
            // ---- MMA + partial epilogue on buf; 7 mtiles x 2 n-halves ----
            int mt = wid >> 1, half = wid & 1;
            uint32_t af[9][4];
            uint32_t a_base = sb + SM_A0 + (uint32_t)(buf*34048)
                            + (uint32_t)((mt*16 + (lane & 15))*304 + ((lane >> 4)*8)*2);
            #pragma unroll
            for (int k=0;k<9;k++)
                asm volatile("ldmatrix.sync.aligned.m8n8.x4.shared.b16 {%0,%1,%2,%3}, [%4];"
                    : "=r"(af[k][0]),"=r"(af[k][1]),"=r"(af[k][2]),"=r"(af[k][3])
                    : "r"(a_base + (uint32_t)(k*32)));
            uint32_t bl_lane = (uint32_t)((lane & 7)*304 + ((lane >> 3) & 1)*16);
            uint32_t b_base = sb + SM_B + bl_lane;
            int lq = lane & 3, lg = lane >> 2;
            int rlow = mt*16 + lg, rhigh = rlow + 8;
            const float* ub   = (const float*)(smc + SM_U) + buf*272;
            const float* u_lo = ub + ((rlow  < 50) ? 0 : 132);
            const float* u_hi = ub + ((rhigh < 50) ? 0 : 132);
            const float* wts  = (const float*)(smc + SM_WT);
            float p_lo = 0.f, p_hi = 0.f;
            if (half == 0){
                do_chunk<4>(b_base, 0, af, u_lo, u_hi, wts, lq, p_lo, p_hi);
                do_chunk<4>(b_base, 4, af, u_lo, u_hi, wts, lq, p_lo, p_hi);
                do_chunk<1>(b_base, 8, af, u_lo, u_hi, wts, lq, p_lo, p_hi);
            } else {
                do_chunk<4>(b_base,  9, af, u_lo, u_hi, wts, lq, p_lo, p_hi);
                do_chunk<4>(b_base, 13, af, u_lo, u_hi, wts, lq, p_lo, p_hi);
            }
            p_lo += __shfl_xor_sync(0xffffffffu, p_lo, 1);
            p_lo += __shfl_xor_sync(0xffffffffu, p_lo, 2);
            p_hi += __shfl_xor_sync(0xffffffffu, p_hi, 1);
            p_hi += __shfl_xor_sync(0xffffffffu, p_hi, 2);
            if (lq == 0){
                float* psh = (float*)(smc + SM_PSH) + half*112;
                psh[rlow]  = p_lo;
                psh[rhigh] = p_hi;
            }
        }
        __syncthreads();       // psh ready
        if (tid < 100){
            const float* psh = (const float*)(smc + SM_PSH);
            float v = psh[tid] + psh[112 + tid];
            ((float*)(smc + SM_SPS))[tid] = fmaxf(v,0.f) + log1pf(expf(-fabsf(v)));
        }
        __syncthreads();       // sps ready
        if (tid < 2){
            const float* sps = (const float*)(smc + SM_SPS) + tid*50;
            float s = 0.f;
            #pragma unroll
            for (int q=0;q<50;q++) s += sps[q];
            out_mean[2*pair + tid] = s * 0.02f;
        }
    }
}

// ---------------------------------------------------------------- launch
extern "C" void kernel_launch(void* const* d_in, const int* in_sizes, int n_in,
                              void* d_out, int out_size)
{
    const int*   etype  = (const int*)  d_in[0];
    const float* etime  = (const float*)d_in[1];
    const float* Wt     = (const float*)d_in[3];
    const float* temb   = (const float*)d_in[4];
    const float* Wg     = (const float*)d_in[5];
    const float* bg     = (const float*)d_in[6];
    const float* Wl     = (const float*)d_in[7];
    const float* bl     = (const float*)d_in[8];
    const float* gamma  = (const float*)d_in[9];
    const float* beta   = (const float*)d_in[10];
    const float* W_in   = (const float*)d_in[11];
    const float* W_noise= (const float*)d_in[12];
    const float* w_time = (const float*)d_in[13];
    const float* W_pred = (const float*)d_in[14];
    float* out = (float*)d_out;          // [0,16384): mean ; then mark_probs

    k_prep<<<512 + 81, 256>>>(etype, etime, Wt, temb, Wg, Wl, W_noise);
    k_rng<<<4096, 256>>>();                       // zero-smem: full occupancy
    cudaFuncSetAttribute(k_attn, cudaFuncAttributeMaxDynamicSharedMemorySize, AT_FLOATS*4);
    k_attn<<<512, 256, AT_FLOATS*4>>>(etime, bg, bl, gamma, beta,
                                      W_in, W_pred, out + NROWS);
    cudaFuncSetAttribute(k_gan, cudaFuncAttributeMaxDynamicSharedMemorySize, SM_TOT);
    k_gan<<<148, 512, SM_TOT>>>(w_time, out);
}

// round 16
// speedup vs baseline: 1.1632x; 1.1632x over previous
#include <cuda_runtime.h>
#include <cuda_bf16.h>
#include <cuda_fp16.h>
#include <math.h>
#include <stdint.h>

#define NROWS 16384      // B*L = 32*512
#define Hh 132           // hidden dim

// scratch (static device globals are allowed)
__device__ float  g_hv [NROWS*Hh];
__device__ float4 g_misc[NROWS];          // dg, dg2, dl, dl2
__device__ float  g_u  [NROWS*Hh];        // hidden @ W_in.T
// fp16 image of W_noise, [n=136 pad][k stride 152], zero-padded
__device__ __align__(16) __half g_Bf[136*152];
// pre-generated noise tiles: per pair 112 rows x 304B (k stride 152 fp16), pads zeroed
__device__ __align__(16) uint2 g_noise[(size_t)8192*4256];   // 279 MB

// ---------------------------------------------------------------- kernel 1
// blocks [0,512): positional/type prep (32 rows each); blocks [512,593): W image
__global__ void k_prep(const int* __restrict__ etype,
                       const float* __restrict__ etime,
                       const float* __restrict__ Wt,
                       const float* __restrict__ temb,
                       const float* __restrict__ Wg,
                       const float* __restrict__ Wl,
                       const float* __restrict__ Wn)
{
    int bx = blockIdx.x;
    int tid = threadIdx.x;
    if (bx >= 512){
        int idx = (bx - 512)*256 + tid;
        if (idx >= 136*152) return;
        int n = idx / 152, k = idx % 152;
        float v = (n < 132 && k < 132) ? Wn[n*132 + k] : 0.f;
        g_Bf[idx] = __float2half_rn(v);
        return;
    }
    int k  = tid & 63;
    int rg = tid >> 6;               // 0..3
    float argf = (float)(2*k) * (-0.07195578415606393f);
    float dv   = (float)exp((double)argf);   // one FP64 exp per thread
    float wtk  = Wt[k];
    int row0 = bx*32 + rg*8;
    #pragma unroll 1
    for (int rr = 0; rr < 8; rr++){
        int row = row0 + rr;
        int l   = row & 511;
        float t   = etime[row];
        float phi = __fmul_rn(t, wtk);
        float arc = __fmul_rn((float)l, dv);
        float x   = __fadd_rn(arc, phi);     // identical f32 value as reference
        double xd = (double)x;
        double q  = rint(xd * 0.15915494309189535);
        double r  = xd - q*6.283185307179586477;
        r -= q*2.4492935982947064e-16;
        float rf = (float)r;
        float s, c;
        __sincosf(rf, &s, &c);
        g_hv[row*Hh + k]      = s;
        g_hv[row*Hh + 64 + k] = c;
        int ty = etype[row];
        if (k < 4) g_hv[row*Hh + 128 + k] = temb[ty*4 + k];
        if (k == 0){
            float te0=temb[ty*4+0], te1=temb[ty*4+1], te2=temb[ty*4+2], te3=temb[ty*4+3];
            float dg  = te0*Wg[0]+te1*Wg[1]+te2*Wg[2]+te3*Wg[3];
            float dg2 = te0*Wg[4]+te1*Wg[5]+te2*Wg[6]+te3*Wg[7];
            float dl  = te0*Wl[0]+te1*Wl[1]+te2*Wl[2]+te3*Wl[3];
            float dl2 = te0*Wl[4]+te1*Wl[5]+te2*Wl[6]+te3*Wl[7];
            g_misc[row] = make_float4(dg, dg2, dl, dl2);
        }
    }
}

// ---------------------------------------------------------------- RNG
__device__ __forceinline__ void tf_round(uint32_t& x0, uint32_t& x1, int r){
    x0 += x1; x1 = __funnelshift_l(x1, x1, r); x1 ^= x0;
}
__device__ __forceinline__ float tf_uniform(uint32_t idx){
    const uint32_t k0 = 0u, k1 = 42u, k2 = 0x1BD11BDAu ^ 42u;
    uint32_t x0 = 0u, x1 = idx;
    x0 += k0; x1 += k1;
    tf_round(x0,x1,13); tf_round(x0,x1,15); tf_round(x0,x1,26); tf_round(x0,x1, 6);
    x0 += k1; x1 += k2 + 1u;
    tf_round(x0,x1,17); tf_round(x0,x1,29); tf_round(x0,x1,16); tf_round(x0,x1,24);
    x0 += k2; x1 += k0 + 2u;
    tf_round(x0,x1,13); tf_round(x0,x1,15); tf_round(x0,x1,26); tf_round(x0,x1, 6);
    x0 += k0; x1 += k1 + 3u;
    tf_round(x0,x1,17); tf_round(x0,x1,29); tf_round(x0,x1,16); tf_round(x0,x1,24);
    x0 += k1; x1 += k2 + 4u;
    tf_round(x0,x1,13); tf_round(x0,x1,15); tf_round(x0,x1,26); tf_round(x0,x1, 6);
    x0 += k2; x1 += k0 + 5u;
    uint32_t bits = x0 ^ x1;
    return __uint_as_float((bits >> 9) | 0x3f800000u) - 1.0f;
}

// fill one pair's noise tile in gmem (112 rows x 304B, pads zero), fp16
__device__ __forceinline__ void rng_pair_gmem(int pair, int t){
    uint2* dst = g_noise + (size_t)pair*4256;
    uint32_t base = (uint32_t)pair * 13200u;
    unsigned row = (unsigned)t / 33u;
    unsigned grp = (unsigned)t - row*33u;
    for (unsigned e = t; e < 3300u; e += 256){
        uint32_t idx = base + row*132u + grp*4u;
        float f0 = tf_uniform(idx);
        float f1 = tf_uniform(idx + 1u);
        float f2 = tf_uniform(idx + 2u);
        float f3 = tf_uniform(idx + 3u);
        __half2 h01 = __floats2half2_rn(f0, f1);
        __half2 h23 = __floats2half2_rn(f2, f3);
        dst[row*38u + grp] = make_uint2(*(uint32_t*)&h01, *(uint32_t*)&h23);
        grp += 25u; row += 7u;                 // e += 256 == 7*33 + 25
        if (grp >= 33u){ grp -= 33u; row += 1u; }
    }
    // pads: k in [132,152) for rows 0..99 (5 uint2/row), rows 100..111 full (456 uint2)
    for (unsigned e = t; e < 956u; e += 256){
        unsigned o;
        if (e < 500u){ unsigned r2 = e/5u, q = e - r2*5u; o = r2*38u + 33u + q; }
        else o = 3800u + (e - 500u);
        dst[o] = make_uint2(0u, 0u);
    }
}

// ---------------------------------------------------------------- kernel 1b
// dedicated RNG chunk: 1024 blocks x 2 pairs = 2048 pairs starting at pair0
__global__ void __launch_bounds__(256)
k_rng(int pair0)
{
    int idx = pair0 + 2*blockIdx.x;
    int tid = threadIdx.x;
    rng_pair_gmem(idx,     tid);
    rng_pair_gmem(idx + 1, tid);
}

// ---------------------------------------------------------------- kernel 2
// attention + LayerNorm + head (u GEMM + mark softmax); grid = 512
#define AT_HV   0          // 4224 (32x132)
#define AT_SCS  4224       // 1056 (32x33)
#define AT_WIN  5280       // 17424 (WinT [k][132])
#define AT_WP   22704      // 2640  (WpT  [k][20])
#define AT_MIS  25344      // 192: tj,dgj,dlj,tis,dg2s,dl2s
#define AT_FLOATS 25536    // 102144 bytes
__global__ void k_attn(const float* __restrict__ etime,
                       const float* __restrict__ bgp,
                       const float* __restrict__ blp,
                       const float* __restrict__ gamma,
                       const float* __restrict__ beta,
                       const float* __restrict__ W_in,
                       const float* __restrict__ W_pred,
                       float* __restrict__ out_mark)
{
    extern __shared__ __align__(16) float smA[];
    int bx = blockIdx.x;
    int tid = threadIdx.x;
    float* hvsh = smA + AT_HV;
    float* scs  = smA + AT_SCS;
    float* WinT = smA + AT_WIN;
    float* WpT  = smA + AT_WP;
    float* tj   = smA + AT_MIS;
    float* dgj  = tj + 32;
    float* dlj  = dgj + 32;
    float* tis  = dlj + 32;
    float* dg2s = tis + 32;
    float* dl2s = dg2s + 32;

    int it = bx & 15, b = bx >> 4;
    int i0 = it*32;
    int g = tid >> 5, lane = tid & 31;
    float bg = bgp[0], bl = blp[0];
    if (tid < 32){
        int ri = b*512 + i0 + tid;
        tis[tid] = etime[ri];
        float4 m = g_misc[ri];
        dg2s[tid] = m.y; dl2s[tid] = m.w;
    }
    // stage W_in^T and W_pred^T
    for (int o = tid; o < 17424; o += 256){
        float v = W_in[o];  int hp = o/132, k = o%132;
        WinT[k*132 + hp] = v;
    }
    for (int o = tid; o < 2640; o += 256){
        float v = W_pred[o]; int c = o/132, k = o%132;
        WpT[k*20 + c] = v;
    }
    float acc[20];
    #pragma unroll
    for (int m=0;m<20;m++) acc[m]=0.f;
    int c0 = g*4;     // warp g owns float4 groups c0..c0+3 (+1 extra for g==7)

    for (int jt = 0; jt <= it; jt++) {
        int j0 = jt*32;
        __syncthreads();                         // prev FMA done; tis ready
        {
            const float4* src4 = (const float4*)(g_hv + (size_t)(b*512 + j0)*132);
            float4* d4 = (float4*)hvsh;
            for (int o = tid; o < 1056; o += 256) d4[o] = src4[o];
        }
        if (tid < 32) {
            int rj = b*512 + j0 + tid;
            tj[tid] = etime[rj];
            float4 mj = g_misc[rj];
            dgj[tid] = mj.x; dlj[tid] = mj.z;
        }
        __syncthreads();
        // score phase: 1024 scores over 256 threads (computed ONCE per tile)
        #pragma unroll
        for (int e = tid; e < 1024; e += 256){
            int ii = e >> 5, jj = e & 31;
            float td  = fabsf(tj[jj] - tis[ii]);
            float gg  = dgj[jj] + dg2s[ii] + bg;
            float sig = 1.f/(1.f + expf(-gg));
            float ll  = dlj[jj] + dl2s[ii] + bl;
            float spv = fmaxf(ll,0.f) + log1pf(expf(-fabsf(ll)));
            float ls  = spv + 1e-6f;
            float sc  = sig / (1.f + td*td/(2.f*ls*ls));
            scs[ii*33 + jj] = (j0 + jj < i0 + ii) ? sc : 0.f;
        }
        __syncthreads();
        #pragma unroll 1
        for (int j = 0; j < 32; j++) {
            float sc = scs[lane*33 + j];
            const float4* hv4 = (const float4*)hvsh + j*33 + c0;
            float4 v0 = hv4[0], v1 = hv4[1], v2 = hv4[2], v3 = hv4[3];
            acc[0]+=sc*v0.x;  acc[1]+=sc*v0.y;  acc[2]+=sc*v0.z;  acc[3]+=sc*v0.w;
            acc[4]+=sc*v1.x;  acc[5]+=sc*v1.y;  acc[6]+=sc*v1.z;  acc[7]+=sc*v1.w;
            acc[8]+=sc*v2.x;  acc[9]+=sc*v2.y;  acc[10]+=sc*v2.z; acc[11]+=sc*v2.w;
            acc[12]+=sc*v3.x; acc[13]+=sc*v3.y; acc[14]+=sc*v3.z; acc[15]+=sc*v3.w;
            if (g == 7){
                float4 v4 = hv4[4];
                acc[16]+=sc*v4.x; acc[17]+=sc*v4.y; acc[18]+=sc*v4.z; acc[19]+=sc*v4.w;
            }
        }
    }
    __syncthreads();
    {
        float4* w4 = (float4*)hvsh + lane*33 + c0;
        w4[0] = make_float4(acc[0],acc[1],acc[2],acc[3]);
        w4[1] = make_float4(acc[4],acc[5],acc[6],acc[7]);
        w4[2] = make_float4(acc[8],acc[9],acc[10],acc[11]);
        w4[3] = make_float4(acc[12],acc[13],acc[14],acc[15]);
        if (g == 7) w4[4] = make_float4(acc[16],acc[17],acc[18],acc[19]);
    }
    __syncthreads();
    // LayerNorm in place (warp-private rows g*4..g*4+3)
    for (int rr=0; rr<4; rr++) {
        int rloc = g*4+rr;
        float s = 0.f;
        #pragma unroll
        for (int q=0;q<5;q++){ int h=lane+32*q; if(h<Hh) s += hvsh[rloc*Hh+h]; }
        #pragma unroll
        for (int off=16;off>0;off>>=1) s += __shfl_xor_sync(0xffffffffu, s, off);
        float mu = s * (1.f/132.f);
        float v = 0.f;
        #pragma unroll
        for (int q=0;q<5;q++){ int h=lane+32*q; if(h<Hh){ float d=hvsh[rloc*Hh+h]-mu; v += d*d; } }
        #pragma unroll
        for (int off=16;off>0;off>>=1) v += __shfl_xor_sync(0xffffffffu, v, off);
        float rs = rsqrtf(v*(1.f/132.f) + 1e-6f);
        #pragma unroll
        for (int q=0;q<5;q++){
            int h=lane+32*q;
            if (h<Hh) hvsh[rloc*Hh+h] = (hvsh[rloc*Hh+h]-mu)*rs*gamma[h] + beta[h];
        }
    }
    __syncwarp();
    // head: u = hid @ W_in^T (store g_u), mark softmax (output)
    #pragma unroll 1
    for (int rr=0; rr<4; rr++){
        int rloc = g*4+rr;
        int row  = b*512 + i0 + rloc;
        float4 a4 = make_float4(0.f,0.f,0.f,0.f);
        float aex = 0.f, lg = 0.f;
        #pragma unroll 2
        for (int k=0;k<132;k++){
            float hk = hvsh[rloc*132+k];
            float4 wv = *(const float4*)(WinT + k*132 + 4*lane);
            a4.x += hk*wv.x; a4.y += hk*wv.y; a4.z += hk*wv.z; a4.w += hk*wv.w;
            if (lane < 4)  aex += hk * WinT[k*132 + 128 + lane];
            if (lane < 20) lg  += hk * WpT[k*20 + lane];
        }
        *(float4*)(g_u + (size_t)row*132 + 4*lane) = a4;
        if (lane < 4) g_u[(size_t)row*132 + 128 + lane] = aex;
        float v = (lane<20) ? lg : -3.4e38f;
        #pragma unroll
        for (int off=16;off>0;off>>=1) v = fmaxf(v, __shfl_xor_sync(0xffffffffu, v, off));
        float e = (lane<20) ? expf(lg - v) : 0.f;
        float ssum = e;
        #pragma unroll
        for (int off=16;off>0;off>>=1) ssum += __shfl_xor_sync(0xffffffffu, ssum, off);
        if (lane<20) out_mark[(size_t)row*20+lane] = e/ssum;
    }
}

// ---------------------------------------------------------------- kernel 4
// A (noise) layout: [row 0..111][k stride 152] fp16, 304B row stride.
#define SM_A0   0
#define SM_A1   34048
#define SM_B    68096        // fp16 W image, 41344 bytes
#define SM_U    109440       // [2][272] floats (264 used + zero pad)
#define SM_WT   111616       // 136 floats (132..135 = 0)
#define SM_PSH  112160       // [2][112] partial row sums
#define SM_SPS  113056       // 112 floats (rows 0..99 used)
#define SM_TOT  113504

__device__ __forceinline__ uint32_t smem_u32(const void* p){
    uint32_t a;
    asm("{ .reg .u64 t; cvta.to.shared.u64 t, %1; cvt.u32.u64 %0, t; }" : "=r"(a) : "l"(p));
    return a;
}

__device__ __forceinline__ void prefetch(uint32_t sb, int buf, int pair, int tid){
    const uint4* src = ((const uint4*)g_noise) + (size_t)pair*2128;
    uint32_t dst = sb + SM_A0 + buf*34048;
    #pragma unroll 1
    for (int o = tid; o < 2128; o += 512)
        asm volatile("cp.async.cg.shared.global [%0], [%1], 16;"
                     :: "r"(dst + o*16), "l"(src + o));
    if (tid < 66){
        const uint4* us = (const uint4*)(g_u + (size_t)pair*264) + tid;
        asm volatile("cp.async.cg.shared.global [%0], [%1], 16;"
                     :: "r"(sb + SM_U + buf*1088 + tid*16), "l"(us));
    }
}

template<int CNT>
__device__ __forceinline__ void do_chunk(
    uint32_t b_base, int nbase,
    const uint32_t af[9][4],
    const float* u_lo, const float* u_hi, const float* wts,
    int lq, float& p_lo, float& p_hi)
{
    float d[CNT][4];
    #pragma unroll
    for (int j=0;j<CNT;j++){ d[j][0]=0.f; d[j][1]=0.f; d[j][2]=0.f; d[j][3]=0.f; }
    #pragma unroll
    for (int j=0;j<CNT;j++){
        uint32_t bo = (uint32_t)((nbase+j)*2432);
        #pragma unroll
        for (int k=0;k<9;k++){
            uint32_t b0,b1;
            asm volatile("ldmatrix.sync.aligned.m8n8.x2.shared.b16 {%0,%1}, [%2];"
                : "=r"(b0),"=r"(b1) : "r"(b_base + bo + (uint32_t)(k*32)));
            asm("mma.sync.aligned.m16n8k16.row.col.f32.f16.f16.f32 "
                "{%0,%1,%2,%3}, {%4,%5,%6,%7}, {%8,%9}, {%0,%1,%2,%3};"
                : "+f"(d[j][0]),"+f"(d[j][1]),"+f"(d[j][2]),"+f"(d[j][3])
                : "r"(af[k][0]),"r"(af[k][1]),"r"(af[k][2]),"r"(af[k][3]),
                  "r"(b0),"r"(b1));
        }
    }
    #pragma unroll
    for (int j=0;j<CNT;j++){
        int c0 = (nbase+j)*8 + lq*2;
        float w0 = wts[c0], w1 = wts[c0+1];
        p_lo += fmaxf(d[j][0]+u_lo[c0],0.f)*w0 + fmaxf(d[j][1]+u_lo[c0+1],0.f)*w1;
        p_hi += fmaxf(d[j][2]+u_hi[c0],0.f)*w0 + fmaxf(d[j][3]+u_hi[c0+1],0.f)*w1;
    }
}

__global__ void __launch_bounds__(512, 1)
k_gan(const float* __restrict__ w_time, float* __restrict__ out_mean,
      int P0, int P1)
{
    extern __shared__ char smc[];
    uint32_t sb = smem_u32(smc);
    int tid = threadIdx.x;
    int wid = tid >> 5, lane = tid & 31;
    int bid = blockIdx.x;

    // init: copy B image, wt, zero ONLY u pad words (live u words are cp.async targets)
    {
        const uint4* sB = (const uint4*)g_Bf;
        uint4* dB = (uint4*)(smc + SM_B);
        for (int o = tid; o < 2584; o += 512) dB[o] = sB[o];
        float* wt = (float*)(smc + SM_WT);
        if (tid < 136) wt[tid] = (tid < 132) ? w_time[tid] : 0.f;
        float* uu = (float*)(smc + SM_U);
        if (tid < 8){ uu[264 + tid] = 0.f; uu[536 + tid] = 0.f; }
    }
    __syncthreads();   // init stores complete before async writes to SM_U region
    // prologue prefetch (buf 0)
    prefetch(sb, 0, P0 + bid, tid);
    asm volatile("cp.async.commit_group;" ::: "memory");

    for (int iter = 0;; iter++){
        int pair = P0 + bid + 148*iter;
        if (pair >= P1) break;
        int buf = iter & 1;
        int nextpair = pair + 148;

        if (nextpair < P1){
            prefetch(sb, buf^1, nextpair, tid);
            asm volatile("cp.async.commit_group;" ::: "memory");
            asm volatile("cp.async.wait_group 1;" ::: "memory");
        } else {
            asm volatile("cp.async.wait_group 0;" ::: "memory");
        }
        __syncthreads();       // A(buf), u(buf) visible to all threads

        if (wid < 14){
            // ---- MMA + partial epilogue on buf; 7 mtiles x 2 n-halves ----
            int mt = wid >> 1, half = wid & 1;
            uint32_t af[9][4];
            uint32_t a_base = sb + SM_A0 + (uint32_t)(buf*34048)
                            + (uint32_t)((mt*16 + (lane & 15))*304 + ((lane >> 4)*8)*2);
            #pragma unroll
            for (int k=0;k<9;k++)
                asm volatile("ldmatrix.sync.aligned.m8n8.x4.shared.b16 {%0,%1,%2,%3}, [%4];"
                    : "=r"(af[k][0]),"=r"(af[k][1]),"=r"(af[k][2]),"=r"(af[k][3])
                    : "r"(a_base + (uint32_t)(k*32)));
            uint32_t bl_lane = (uint32_t)((lane & 7)*304 + ((lane >> 3) & 1)*16);
            uint32_t b_base = sb + SM_B + bl_lane;
            int lq = lane & 3, lg = lane >> 2;
            int rlow = mt*16 + lg, rhigh = rlow + 8;
            const float* ub   = (const float*)(smc + SM_U) + buf*272;
            const float* u_lo = ub + ((rlow  < 50) ? 0 : 132);
            const float* u_hi = ub + ((rhigh < 50) ? 0 : 132);
            const float* wts  = (const float*)(smc + SM_WT);
            float p_lo = 0.f, p_hi = 0.f;
            if (half == 0){
                do_chunk<4>(b_base, 0, af, u_lo, u_hi, wts, lq, p_lo, p_hi);
                do_chunk<4>(b_base, 4, af, u_lo, u_hi, wts, lq, p_lo, p_hi);
                do_chunk<1>(b_base, 8, af, u_lo, u_hi, wts, lq, p_lo, p_hi);
            } else {
                do_chunk<4>(b_base,  9, af, u_lo, u_hi, wts, lq, p_lo, p_hi);
                do_chunk<4>(b_base, 13, af, u_lo, u_hi, wts, lq, p_lo, p_hi);
            }
            p_lo += __shfl_xor_sync(0xffffffffu, p_lo, 1);
            p_lo += __shfl_xor_sync(0xffffffffu, p_lo, 2);
            p_hi += __shfl_xor_sync(0xffffffffu, p_hi, 1);
            p_hi += __shfl_xor_sync(0xffffffffu, p_hi, 2);
            if (lq == 0){
                float* psh = (float*)(smc + SM_PSH) + half*112;
                psh[rlow]  = p_lo;
                psh[rhigh] = p_hi;
            }
        }
        __syncthreads();       // psh ready
        if (tid < 100){
            const float* psh = (const float*)(smc + SM_PSH);
            float v = psh[tid] + psh[112 + tid];
            ((float*)(smc + SM_SPS))[tid] = fmaxf(v,0.f) + log1pf(expf(-fabsf(v)));
        }
        __syncthreads();       // sps ready
        if (tid < 2){
            const float* sps = (const float*)(smc + SM_SPS) + tid*50;
            float s = 0.f;
            #pragma unroll
            for (int q=0;q<50;q++) s += sps[q];
            out_mean[2*pair + tid] = s * 0.02f;
        }
    }
}

// ---------------------------------------------------------------- launch
extern "C" void kernel_launch(void* const* d_in, const int* in_sizes, int n_in,
                              void* d_out, int out_size)
{
    const int*   etype  = (const int*)  d_in[0];
    const float* etime  = (const float*)d_in[1];
    const float* Wt     = (const float*)d_in[3];
    const float* temb   = (const float*)d_in[4];
    const float* Wg     = (const float*)d_in[5];
    const float* bg     = (const float*)d_in[6];
    const float* Wl     = (const float*)d_in[7];
    const float* bl     = (const float*)d_in[8];
    const float* gamma  = (const float*)d_in[9];
    const float* beta   = (const float*)d_in[10];
    const float* W_in   = (const float*)d_in[11];
    const float* W_noise= (const float*)d_in[12];
    const float* w_time = (const float*)d_in[13];
    const float* W_pred = (const float*)d_in[14];
    float* out = (float*)d_out;          // [0,16384): mean ; then mark_probs

    cudaFuncSetAttribute(k_attn, cudaFuncAttributeMaxDynamicSharedMemorySize, AT_FLOATS*4);
    cudaFuncSetAttribute(k_gan,  cudaFuncAttributeMaxDynamicSharedMemorySize, SM_TOT);

    // fork a second stream for the RNG chain (standard capture fork/join)
    cudaStream_t s2;
    cudaStreamCreateWithFlags(&s2, cudaStreamNonBlocking);
    cudaEvent_t evF, evR[4];
    cudaEventCreateWithFlags(&evF, cudaEventDisableTiming);
    for (int c = 0; c < 4; c++) cudaEventCreateWithFlags(&evR[c], cudaEventDisableTiming);

    cudaEventRecord(evF, 0);
    cudaStreamWaitEvent(s2, evF, 0);
    for (int c = 0; c < 4; c++){
        k_rng<<<1024, 256, 0, s2>>>(2048*c);
        cudaEventRecord(evR[c], s2);
    }

    k_prep<<<512 + 81, 256>>>(etype, etime, Wt, temb, Wg, Wl, W_noise);
    k_attn<<<512, 256, AT_FLOATS*4>>>(etime, bg, bl, gamma, beta,
                                      W_in, W_pred, out + NROWS);
    for (int c = 0; c < 4; c++){
        cudaStreamWaitEvent(0, evR[c], 0);
        k_gan<<<148, 512, SM_TOT>>>(w_time, out, 2048*c, 2048*(c+1));
    }
    // NOTE: s2/events intentionally not destroyed here — destroying a stream
    // that participated in an active capture is illegal; tiny one-time leak.
}